// round 1
// baseline (speedup 1.0000x reference)
#include <cuda_runtime.h>
#include <math.h>

#define D      64
#define CAP    128           // max in-degree slots per node (Poisson(32): P(>=128) ~ e^-81)
#define MAXN   100000
#define MAXB   1024

// ---------------- static device scratch (no allocation allowed) ----------------
__device__ float g_bufA[MAXN * D];        // node features "out"
__device__ float g_bufB[MAXN * D];        // transformed features "h"
__device__ int   g_cnt[MAXN];             // in-degree (edge count per target)
__device__ int   g_csr_row[MAXN * CAP];   // source node per (target, slot)
__device__ float g_csr_w[MAXN * CAP];     // norm per (target, slot)
__device__ float g_dinv[MAXN];
__device__ float g_dinv2[MAXN];
__device__ float g_e[MAXN];               // attention logits
__device__ int   g_start[MAXB];           // first node index of each graph
__device__ float g_hl[MAXB * D];
__device__ float g_cl[MAXB * D];
__device__ float g_qstar[MAXB * 2 * D];

__device__ __forceinline__ float sigmoidf(float x) { return 1.0f / (1.0f + expf(-x)); }

// ---------------- build phase ----------------
__global__ void k_zero_cnt(int N) {
    int i = blockIdx.x * blockDim.x + threadIdx.x;
    if (i < N) g_cnt[i] = 0;
}

__global__ void k_build(const int* __restrict__ ei, int E) {
    int e = blockIdx.x * blockDim.x + threadIdx.x;
    if (e >= E) return;
    int r = ei[e];        // source
    int c = ei[E + e];    // target
    int slot = atomicAdd(&g_cnt[c], 1);
    if (slot < CAP) g_csr_row[c * CAP + slot] = r;
}

__global__ void k_dinv(int N) {
    int n = blockIdx.x * blockDim.x + threadIdx.x;
    if (n >= N) return;
    float deg = (float)(g_cnt[n] + 1);   // +1 self loop
    float d = rsqrtf(deg);
    g_dinv[n] = d;
    g_dinv2[n] = d * d;
}

__global__ void k_weights(int N) {
    int i = blockIdx.x * blockDim.x + threadIdx.x;
    if (i >= N * CAP) return;
    int n = i >> 7;
    int s = i & (CAP - 1);
    int cn = g_cnt[n]; if (cn > CAP) cn = CAP;
    if (s < cn) {
        g_csr_w[i] = g_dinv[g_csr_row[i]] * g_dinv[n];
    }
}

// out0 = relu(x @ W0 + b0)
__global__ void k_init_feat(const float* __restrict__ x, const float* __restrict__ W0,
                            const float* __restrict__ b0, int N) {
    int idx = blockIdx.x * blockDim.x + threadIdx.x;
    if (idx >= N * D) return;
    int n = idx >> 6, c = idx & 63;
    float acc = b0[c];
    const float* xr = x + n * 15;
#pragma unroll
    for (int k = 0; k < 15; k++) acc += xr[k] * W0[k * D + c];
    g_bufA[idx] = fmaxf(acc, 0.0f);
}

// ---------------- propagation: h = out @ Wc  (bufA -> bufB) ----------------
__global__ void k_gemm(const float* __restrict__ W, int N) {
    __shared__ float xs[64][68];   // padded: 16B-aligned rows, conflict-free
    __shared__ float ws[64][64];
    int t = threadIdx.x;           // 256 threads
    int base = blockIdx.x * 64;

    for (int i = t; i < 1024; i += 256) {       // 64x64 floats as float4
        int row = i >> 4, c4 = (i & 15) << 2;
        *(float4*)&ws[row][c4] = *(const float4*)&W[row * 64 + c4];
        int gr = base + row;
        float4 v = make_float4(0.f, 0.f, 0.f, 0.f);
        if (gr < N) v = *(const float4*)&g_bufA[(size_t)gr * 64 + c4];
        *(float4*)&xs[row][c4] = v;
    }
    __syncthreads();

    int rr = t >> 4;     // row group (0..15) -> rows rr*4..rr*4+3
    int cc = t & 15;     // col group -> cols cc*4..cc*4+3
    float4 a0 = {0,0,0,0}, a1 = {0,0,0,0}, a2 = {0,0,0,0}, a3 = {0,0,0,0};
#pragma unroll 16
    for (int k = 0; k < 64; k++) {
        float4 w = *(float4*)&ws[k][cc * 4];
        float x0 = xs[rr * 4 + 0][k];
        float x1 = xs[rr * 4 + 1][k];
        float x2 = xs[rr * 4 + 2][k];
        float x3 = xs[rr * 4 + 3][k];
        a0.x += x0 * w.x; a0.y += x0 * w.y; a0.z += x0 * w.z; a0.w += x0 * w.w;
        a1.x += x1 * w.x; a1.y += x1 * w.y; a1.z += x1 * w.z; a1.w += x1 * w.w;
        a2.x += x2 * w.x; a2.y += x2 * w.y; a2.z += x2 * w.z; a2.w += x2 * w.w;
        a3.x += x3 * w.x; a3.y += x3 * w.y; a3.z += x3 * w.z; a3.w += x3 * w.w;
    }
    int r0 = base + rr * 4;
    if (r0 + 0 < N) *(float4*)&g_bufB[(size_t)(r0 + 0) * 64 + cc * 4] = a0;
    if (r0 + 1 < N) *(float4*)&g_bufB[(size_t)(r0 + 1) * 64 + cc * 4] = a1;
    if (r0 + 2 < N) *(float4*)&g_bufB[(size_t)(r0 + 2) * 64 + cc * 4] = a2;
    if (r0 + 3 < N) *(float4*)&g_bufB[(size_t)(r0 + 3) * 64 + cc * 4] = a3;
}

// out = relu( sum_edges norm*h[row] + dinv2[n]*h[n] + bc )   (bufB -> bufA)
// one warp per node, float2 per lane; CSR gather, no atomics.
__global__ void k_agg(const float* __restrict__ bc, int N) {
    int w = (blockIdx.x * blockDim.x + threadIdx.x) >> 5;
    if (w >= N) return;
    int lane = threadIdx.x & 31;
    int n = w;
    int cnt = g_cnt[n]; if (cnt > CAP) cnt = CAP;
    const int*   rows = &g_csr_row[n * CAP];
    const float* wts  = &g_csr_w[n * CAP];
    int c = lane * 2;
    float ax = 0.f, ay = 0.f;
    int s = 0;
    for (; s + 2 <= cnt; s += 2) {
        int   r0 = rows[s],   r1 = rows[s + 1];
        float w0 = wts[s],    w1 = wts[s + 1];
        float2 h0 = *(const float2*)&g_bufB[(size_t)r0 * 64 + c];
        float2 h1 = *(const float2*)&g_bufB[(size_t)r1 * 64 + c];
        ax += w0 * h0.x + w1 * h1.x;
        ay += w0 * h0.y + w1 * h1.y;
    }
    if (s < cnt) {
        int r0 = rows[s]; float w0 = wts[s];
        float2 h0 = *(const float2*)&g_bufB[(size_t)r0 * 64 + c];
        ax += w0 * h0.x; ay += w0 * h0.y;
    }
    float d2 = g_dinv2[n];
    float2 hs = *(const float2*)&g_bufB[(size_t)n * 64 + c];
    ax += d2 * hs.x; ay += d2 * hs.y;
    float2 bv = *(const float2*)&bc[c];
    float2 o;
    o.x = fmaxf(ax + bv.x, 0.f);
    o.y = fmaxf(ay + bv.y, 0.f);
    *(float2*)&g_bufA[(size_t)n * 64 + c] = o;
}

// ---------------- Set2Set ----------------
__global__ void k_start_init(int B, int N) {
    int b = blockIdx.x * blockDim.x + threadIdx.x;
    if (b < B) g_start[b] = N;
}

__global__ void k_boundary(const int* __restrict__ batch, int N) {
    int n = blockIdx.x * blockDim.x + threadIdx.x;
    if (n >= N) return;
    int bn = batch[n];
    if (n == 0 || batch[n - 1] != bn) g_start[bn] = n;
}

__global__ void k_zero_state(int B) {
    int i = blockIdx.x * blockDim.x + threadIdx.x;
    int nd = B * D;
    if (i < nd) { g_hl[i] = 0.f; }
    else if (i < 2 * nd) { g_cl[i - nd] = 0.f; }
    else if (i < 4 * nd) { g_qstar[i - 2 * nd] = 0.f; }
}

// LSTM: gates = q_star @ Wih^T + h_l @ Whh^T + bih + bhh ; update (c,h)
__global__ void k_gates(const float* __restrict__ Wih, const float* __restrict__ Whh,
                        const float* __restrict__ bih, const float* __restrict__ bhh) {
    int b = blockIdx.x, j = threadIdx.x;  // 64 threads
    __shared__ float qs[128];
    __shared__ float hl[64];
    qs[j]      = g_qstar[b * 128 + j];
    qs[j + 64] = g_qstar[b * 128 + 64 + j];
    hl[j]      = g_hl[b * 64 + j];
    __syncthreads();

    float gate[4];
#pragma unroll
    for (int gg = 0; gg < 4; gg++) {
        int row = gg * 64 + j;
        float acc = bih[row] + bhh[row];
        const float4* wr = (const float4*)&Wih[row * 128];
#pragma unroll
        for (int k = 0; k < 32; k++) {
            float4 w4 = wr[k];
            acc += qs[4*k+0] * w4.x + qs[4*k+1] * w4.y + qs[4*k+2] * w4.z + qs[4*k+3] * w4.w;
        }
        const float4* hr = (const float4*)&Whh[row * 64];
#pragma unroll
        for (int k = 0; k < 16; k++) {
            float4 w4 = hr[k];
            acc += hl[4*k+0] * w4.x + hl[4*k+1] * w4.y + hl[4*k+2] * w4.z + hl[4*k+3] * w4.w;
        }
        gate[gg] = acc;
    }
    float ig = sigmoidf(gate[0]);
    float fg = sigmoidf(gate[1]);
    float gv = tanhf(gate[2]);
    float og = sigmoidf(gate[3]);
    float cv = fg * g_cl[b * 64 + j] + ig * gv;
    float hv = og * tanhf(cv);
    g_cl[b * 64 + j] = cv;
    g_hl[b * 64 + j] = hv;
}

// e[n] = dot(out[n], q[batch[n]]) ; one warp per node
__global__ void k_e(const int* __restrict__ batch, int N) {
    int w = (blockIdx.x * blockDim.x + threadIdx.x) >> 5;
    if (w >= N) return;
    int lane = threadIdx.x & 31;
    int n = w;
    int b = batch[n];
    int c = lane * 2;
    float2 ov = *(const float2*)&g_bufA[(size_t)n * 64 + c];
    float2 qv = *(const float2*)&g_hl[(size_t)b * 64 + c];
    float s = ov.x * qv.x + ov.y * qv.y;
#pragma unroll
    for (int o = 16; o; o >>= 1) s += __shfl_xor_sync(0xffffffffu, s, o);
    if (lane == 0) g_e[n] = s;
}

// per-graph: m = max e ; denom = sum exp(e-m) ; r = sum a*out ; q_star = [h_l, r]
__global__ void k_attn(const int* __restrict__ batch, int N) {
    int b = blockIdx.x, tid = threadIdx.x;  // 64 threads
    __shared__ float red[64];
    __shared__ float coeff[64];
    __shared__ float m_s, denom_s;
    int st = g_start[b];

    // phase 1: max
    float local = -INFINITY;
    for (int n = st + tid; n < N; n += 64) {
        if (batch[n] != b) break;
        local = fmaxf(local, g_e[n]);
    }
    red[tid] = local;
    __syncthreads();
    if (tid < 32) {
        float v = fmaxf(red[tid], red[tid + 32]);
#pragma unroll
        for (int o = 16; o; o >>= 1) v = fmaxf(v, __shfl_xor_sync(0xffffffffu, v, o));
        if (tid == 0) m_s = v;
    }
    __syncthreads();
    float m = m_s;

    // phase 2: denom
    float ls = 0.f;
    for (int n = st + tid; n < N; n += 64) {
        if (batch[n] != b) break;
        ls += expf(g_e[n] - m);
    }
    red[tid] = ls;
    __syncthreads();
    if (tid < 32) {
        float v = red[tid] + red[tid + 32];
#pragma unroll
        for (int o = 16; o; o >>= 1) v += __shfl_xor_sync(0xffffffffu, v, o);
        if (tid == 0) denom_s = v;
    }
    __syncthreads();
    float inv = (denom_s > 0.f) ? (1.0f / denom_s) : 0.f;

    // phase 3: r accumulation in chunks of 64 nodes
    float rc = 0.f;
    int c = tid;
    for (int base = st; base < N && batch[base] == b; base += 64) {
        int n = base + tid;
        float cf = 0.f;
        if (n < N && batch[n] == b) cf = expf(g_e[n] - m) * inv;
        coeff[tid] = cf;
        __syncthreads();
        int jmax = N - base; if (jmax > 64) jmax = 64;
        for (int j = 0; j < jmax; j++) {
            rc += coeff[j] * g_bufA[(size_t)(base + j) * 64 + c];
        }
        __syncthreads();
    }
    g_qstar[b * 128 + c]      = g_hl[b * 64 + c];
    g_qstar[b * 128 + 64 + c] = rc;
}

// y = relu(q_star @ W1 + b1) @ W2 + b2
__global__ void k_final(const float* __restrict__ W1, const float* __restrict__ b1,
                        const float* __restrict__ W2, const float* __restrict__ b2,
                        float* __restrict__ y) {
    int b = blockIdx.x, t = threadIdx.x;  // 64 threads
    __shared__ float qs[128];
    __shared__ float hid[64];
    qs[t]      = g_qstar[b * 128 + t];
    qs[t + 64] = g_qstar[b * 128 + 64 + t];
    __syncthreads();
    float acc = b1[t];
#pragma unroll 8
    for (int k = 0; k < 128; k++) acc += qs[k] * W1[k * 64 + t];
    hid[t] = fmaxf(acc, 0.f);
    __syncthreads();
    if (t < 12) {
        float a = b2[t];
#pragma unroll 8
        for (int k = 0; k < 64; k++) a += hid[k] * W2[k * 12 + t];
        y[b * 12 + t] = a;
    }
}

// ---------------- launch ----------------
extern "C" void kernel_launch(void* const* d_in, const int* in_sizes, int n_in,
                              void* d_out, int out_size) {
    const float* x     = (const float*)d_in[0];
    const int*   ei    = (const int*)  d_in[1];
    const int*   batch = (const int*)  d_in[2];
    const float* W0    = (const float*)d_in[3];
    const float* b0    = (const float*)d_in[4];
    const float* Wc    = (const float*)d_in[5];
    const float* bc    = (const float*)d_in[6];
    const float* Wih   = (const float*)d_in[7];
    const float* Whh   = (const float*)d_in[8];
    const float* bih   = (const float*)d_in[9];
    const float* bhh   = (const float*)d_in[10];
    const float* W1    = (const float*)d_in[11];
    const float* b1    = (const float*)d_in[12];
    const float* W2    = (const float*)d_in[13];
    const float* b2    = (const float*)d_in[14];
    float* y = (float*)d_out;

    int N = in_sizes[0] / 15;
    int E = in_sizes[1] / 2;
    int B = out_size / 12;

    // ---- build CSR + normalization (once per launch) ----
    k_zero_cnt<<<(N + 255) / 256, 256>>>(N);
    k_build<<<(E + 255) / 256, 256>>>(ei, E);
    k_dinv<<<(N + 255) / 256, 256>>>(N);
    k_weights<<<(N * CAP + 255) / 256, 256>>>(N);
    k_init_feat<<<(N * D + 255) / 256, 256>>>(x, W0, b0, N);

    // ---- 6 propagation steps ----
    for (int s = 0; s < 6; s++) {
        k_gemm<<<(N + 63) / 64, 256>>>(Wc, N);
        k_agg<<<(N * 32 + 255) / 256, 256>>>(bc, N);
    }

    // ---- Set2Set ----
    k_start_init<<<(B + 255) / 256, 256>>>(B, N);
    k_boundary<<<(N + 255) / 256, 256>>>(batch, N);
    k_zero_state<<<(B * 4 * D + 255) / 256, 256>>>(B);
    for (int s = 0; s < 6; s++) {
        k_gates<<<B, 64>>>(Wih, Whh, bih, bhh);
        k_e<<<(N * 32 + 255) / 256, 256>>>(batch, N);
        k_attn<<<B, 64>>>(batch, N);
    }

    // ---- final MLP ----
    k_final<<<B, 64>>>(W1, b1, W2, b2, y);
}